// round 1
// baseline (speedup 1.0000x reference)
#include <cuda_runtime.h>
#include <cuda_bf16.h>
#include <math.h>

// Problem constants
#define BB 2
#define SS 2048
#define DD 1024
#define HH 16
#define HD 64
#define LL 4
#define MROWS (BB*SS)          // 4096
#define FOURD (4*DD)           // 4096

// Scratch (device globals; no allocation allowed)
__device__ float g_h[MROWS * DD];       // hidden state
__device__ float g_uvqk[MROWS * FOURD]; // uvqk projection
__device__ float g_attn[MROWS * DD];    // attention output
__device__ float g_g[MROWS * DD];       // gated

// ---------------------------------------------------------------------------
// block reduce
// ---------------------------------------------------------------------------
__device__ __forceinline__ float blockReduceSum(float v) {
    __shared__ float red[8];
    int lane = threadIdx.x & 31, wid = threadIdx.x >> 5;
    #pragma unroll
    for (int o = 16; o; o >>= 1) v += __shfl_down_sync(0xFFFFFFFFu, v, o);
    if (lane == 0) red[wid] = v;
    __syncthreads();
    float r = 0.f;
    if (threadIdx.x < (blockDim.x >> 5)) r = red[threadIdx.x];
    if (wid == 0) {
        #pragma unroll
        for (int o = 4; o; o >>= 1) r += __shfl_down_sync(0xFFFFFFFFu, r, o);
        if (lane == 0) red[0] = r;
    }
    __syncthreads();
    return red[0];
}

// ---------------------------------------------------------------------------
// RMS norm: out[row] = w * x[row] * rsqrt(mean(x^2)+eps)
// ---------------------------------------------------------------------------
__global__ void rmsnorm_k(const float* __restrict__ in, const float* __restrict__ w,
                          float* __restrict__ out) {
    int row = blockIdx.x;
    const float* x = in + (size_t)row * DD;
    float ss = 0.f;
    for (int i = threadIdx.x; i < DD; i += blockDim.x) { float v = x[i]; ss += v * v; }
    float tot = blockReduceSum(ss);
    float inv = rsqrtf(tot / (float)DD + 1e-6f);
    for (int i = threadIdx.x; i < DD; i += blockDim.x)
        out[(size_t)row * DD + i] = w[i] * x[i] * inv;
}

// ---------------------------------------------------------------------------
// SGEMM: C = A[M,K] @ W[K,N] + bias (+ res). 128x128 tile, BK=8, 8x8/thread.
// All dims divisible by tile sizes (M=4096, N in {1024,4096}, K=1024).
// ---------------------------------------------------------------------------
template<bool ADD_RES>
__global__ __launch_bounds__(256)
void sgemm_k(int M, int N, int K,
             const float* __restrict__ A, const float* __restrict__ W,
             const float* __restrict__ bias, const float* __restrict__ res,
             float* __restrict__ C) {
    const int BM = 128, BN = 128, BK = 8, TM = 8, TN = 8;
    __shared__ float As[BK][BM];
    __shared__ float Ws[BK][BN];
    int tid = threadIdx.x;
    int brow = blockIdx.y, bcol = blockIdx.x;
    const float* Ab = A + (size_t)brow * BM * K;
    const float* Wb = W + (size_t)bcol * BN;

    int aRow = tid >> 1;            // 0..127
    int aCol4 = (tid & 1) * 4;      // 0 or 4
    int wRow = tid >> 5;            // 0..7
    int wCol4 = (tid & 31) * 4;     // 0..124
    int trow = (tid >> 4) * TM;
    int tcol = (tid & 15) * TN;

    float acc[TM][TN] = {};
    for (int k0 = 0; k0 < K; k0 += BK) {
        float4 a = *reinterpret_cast<const float4*>(Ab + (size_t)aRow * K + k0 + aCol4);
        As[aCol4 + 0][aRow] = a.x; As[aCol4 + 1][aRow] = a.y;
        As[aCol4 + 2][aRow] = a.z; As[aCol4 + 3][aRow] = a.w;
        float4 w = *reinterpret_cast<const float4*>(Wb + (size_t)(k0 + wRow) * N + wCol4);
        *reinterpret_cast<float4*>(&Ws[wRow][wCol4]) = w;
        __syncthreads();
        #pragma unroll
        for (int k = 0; k < BK; k++) {
            float rm[TM], rn[TN];
            #pragma unroll
            for (int i = 0; i < TM; i++) rm[i] = As[k][trow + i];
            #pragma unroll
            for (int j = 0; j < TN; j++) rn[j] = Ws[k][tcol + j];
            #pragma unroll
            for (int i = 0; i < TM; i++)
                #pragma unroll
                for (int j = 0; j < TN; j++) acc[i][j] += rm[i] * rn[j];
        }
        __syncthreads();
    }
    #pragma unroll
    for (int i = 0; i < TM; i++) {
        size_t r = (size_t)brow * BM + trow + i;
        #pragma unroll
        for (int j = 0; j < TN; j += 4) {
            size_t c = (size_t)bcol * BN + tcol + j;
            float4 o;
            o.x = acc[i][j + 0] + bias[c + 0];
            o.y = acc[i][j + 1] + bias[c + 1];
            o.z = acc[i][j + 2] + bias[c + 2];
            o.w = acc[i][j + 3] + bias[c + 3];
            if (ADD_RES) {
                float4 rv = *reinterpret_cast<const float4*>(res + r * N + c);
                o.x += rv.x; o.y += rv.y; o.z += rv.z; o.w += rv.w;
            }
            *reinterpret_cast<float4*>(C + r * N + c) = o;
        }
    }
}

// ---------------------------------------------------------------------------
// RoPE (q,k) + SiLU (u) in-place on uvqk. One block per token.
// ---------------------------------------------------------------------------
__global__ void rope_silu_k(float* __restrict__ uvqk,
                            const float* __restrict__ td,
                            const int* __restrict__ pos_ids) {
    int t = blockIdx.x;  // b*S+s
    __shared__ float cs[32], sn[32];
    if (threadIdx.x < 32) {
        float p = (float)pos_ids[t] + 0.1f * logf(td[t] + 1.0f);
        float invf = expf(-logf(10000.0f) * (float)threadIdx.x / 32.0f);
        float f = p * invf;
        cs[threadIdx.x] = cosf(f);
        sn[threadIdx.x] = sinf(f);
    }
    __syncthreads();
    float* row = uvqk + (size_t)t * FOURD;
    // u = silu(u)
    for (int i = threadIdx.x; i < DD; i += blockDim.x) {
        float v = row[i];
        row[i] = v / (1.0f + expf(-v));
    }
    // rope on q (offset 2D) and k (offset 3D); HD=64, 32 pairs per head
    for (int p = threadIdx.x; p < HH * 32; p += blockDim.x) {
        int hh = p >> 5, i = p & 31;
        int base = 2 * DD + hh * HD + i;
        float c = cs[i], s = sn[i];
        float q1 = row[base], q2 = row[base + 32];
        row[base]      = q1 * c - q2 * s;
        row[base + 32] = q2 * c + q1 * s;
        int base2 = base + DD;
        float k1 = row[base2], k2 = row[base2 + 32];
        row[base2]      = k1 * c - k2 * s;
        row[base2 + 32] = k2 * c + k1 * s;
    }
}

// ---------------------------------------------------------------------------
// Fused causal SiLU attention. grid=(S/64, B*H), 256 threads.
// Tiles: 64 queries x 64 keys, HD=64. ss aliases ksT buffer.
// ---------------------------------------------------------------------------
#define APAD 68
__global__ __launch_bounds__(256)
void attn_k(const float* __restrict__ uvqk, float* __restrict__ out) {
    extern __shared__ float sm[];
    float* qs  = sm;                 // [64][APAD]
    float* kss = sm + 64 * APAD;     // ksT (d-major) then ss (row-major)
    float* vs  = sm + 2 * 64 * APAD; // [64][APAD]

    int qt = blockIdx.x, bh = blockIdx.y;
    int b = bh >> 4, h = bh & 15;
    int q0 = qt * 64;
    int tid = threadIdx.x;
    int ry = (tid >> 4) * 4;
    int cx = (tid & 15) * 4;

    const size_t rstr = FOURD;
    const float* qbase = uvqk + (size_t)(b * SS) * rstr + 2 * DD + h * HD;
    const float* kbase = uvqk + (size_t)(b * SS) * rstr + 3 * DD + h * HD;
    const float* vbase = uvqk + (size_t)(b * SS) * rstr + 1 * DD + h * HD;

    // load q tile
    #pragma unroll
    for (int it = 0; it < 4; it++) {
        int r = (tid >> 4) + it * 16;
        int c4 = (tid & 15) * 4;
        float4 v = *reinterpret_cast<const float4*>(qbase + (size_t)(q0 + r) * rstr + c4);
        *reinterpret_cast<float4*>(&qs[r * APAD + c4]) = v;
    }

    float outacc[4][4] = {};

    for (int kt = 0; kt <= qt; kt++) {
        int k0 = kt * 64;
        __syncthreads();  // prior PV reads done before overwriting kss/vs
        #pragma unroll
        for (int it = 0; it < 4; it++) {
            int r = (tid >> 4) + it * 16;
            int c4 = (tid & 15) * 4;
            float4 kv = *reinterpret_cast<const float4*>(kbase + (size_t)(k0 + r) * rstr + c4);
            kss[(c4 + 0) * APAD + r] = kv.x;
            kss[(c4 + 1) * APAD + r] = kv.y;
            kss[(c4 + 2) * APAD + r] = kv.z;
            kss[(c4 + 3) * APAD + r] = kv.w;
            float4 vv = *reinterpret_cast<const float4*>(vbase + (size_t)(k0 + r) * rstr + c4);
            *reinterpret_cast<float4*>(&vs[r * APAD + c4]) = vv;
        }
        __syncthreads();

        // scores: s[i][j] = sum_d q[i][d]*k[j][d]
        float s[4][4] = {};
        #pragma unroll 8
        for (int d = 0; d < 64; d++) {
            float qf[4], kf[4];
            #pragma unroll
            for (int i = 0; i < 4; i++) qf[i] = qs[(ry + i) * APAD + d];
            #pragma unroll
            for (int j = 0; j < 4; j++) kf[j] = kss[d * APAD + cx + j];
            #pragma unroll
            for (int i = 0; i < 4; i++)
                #pragma unroll
                for (int j = 0; j < 4; j++) s[i][j] += qf[i] * kf[j];
        }
        // silu + causal mask
        float w[4][4];
        #pragma unroll
        for (int i = 0; i < 4; i++)
            #pragma unroll
            for (int j = 0; j < 4; j++) {
                float v = s[i][j] * 0.125f;
                v = v / (1.0f + expf(-v));
                if (k0 + cx + j > q0 + ry + i) v = 0.0f;
                w[i][j] = v;
            }
        __syncthreads();  // all ksT reads done, safe to overwrite as ss
        #pragma unroll
        for (int i = 0; i < 4; i++)
            #pragma unroll
            for (int j = 0; j < 4; j++)
                kss[(ry + i) * APAD + cx + j] = w[i][j];
        __syncthreads();

        // PV: outacc[i][dd] += ss[i][j] * vs[j][dd]
        #pragma unroll 8
        for (int j = 0; j < 64; j++) {
            float sf[4], vf[4];
            #pragma unroll
            for (int i = 0; i < 4; i++) sf[i] = kss[(ry + i) * APAD + j];
            #pragma unroll
            for (int jj = 0; jj < 4; jj++) vf[jj] = vs[j * APAD + cx + jj];
            #pragma unroll
            for (int i = 0; i < 4; i++)
                #pragma unroll
                for (int jj = 0; jj < 4; jj++) outacc[i][jj] += sf[i] * vf[jj];
        }
    }

    // write out [B,S,D] with head offset
    #pragma unroll
    for (int i = 0; i < 4; i++) {
        size_t o = (size_t)(b * SS + q0 + ry + i) * DD + h * HD + cx;
        float4 v;
        v.x = outacc[i][0]; v.y = outacc[i][1]; v.z = outacc[i][2]; v.w = outacc[i][3];
        *reinterpret_cast<float4*>(out + o) = v;
    }
}

// ---------------------------------------------------------------------------
// gated = rms_norm(attn, gate_w) * u
// ---------------------------------------------------------------------------
__global__ void rmsgate_k(const float* __restrict__ attn, const float* __restrict__ gw,
                          const float* __restrict__ uvqk, float* __restrict__ g) {
    int row = blockIdx.x;
    const float* x = attn + (size_t)row * DD;
    const float* u = uvqk + (size_t)row * FOURD;  // u part at offset 0 (already SiLU'd)
    float ss = 0.f;
    for (int i = threadIdx.x; i < DD; i += blockDim.x) { float v = x[i]; ss += v * v; }
    float tot = blockReduceSum(ss);
    float inv = rsqrtf(tot / (float)DD + 1e-6f);
    for (int i = threadIdx.x; i < DD; i += blockDim.x)
        g[(size_t)row * DD + i] = gw[i] * x[i] * inv * u[i];
}

// ---------------------------------------------------------------------------
// kernel_launch
// ---------------------------------------------------------------------------
extern "C" void kernel_launch(void* const* d_in, const int* in_sizes, int n_in,
                              void* d_out, int out_size) {
    const float* x        = (const float*)d_in[0];
    const float* td       = (const float*)d_in[1];
    // d_in[2] = attn_mask: structurally tril(ones) per setup_inputs -> causal mask applied in-kernel
    const float* uvqk_w   = (const float*)d_in[3];
    const float* uvqk_b   = (const float*)d_in[4];
    const float* gate_w   = (const float*)d_in[5];
    const float* out_w    = (const float*)d_in[6];
    const float* out_b    = (const float*)d_in[7];
    const float* in_nw    = (const float*)d_in[8];
    const float* last_nw  = (const float*)d_in[9];
    const int*   pos_ids  = (const int*)d_in[10];
    float* out = (float*)d_out;

    void *ph, *puvqk, *pattn, *pg;
    cudaGetSymbolAddress(&ph, g_h);
    cudaGetSymbolAddress(&puvqk, g_uvqk);
    cudaGetSymbolAddress(&pattn, g_attn);
    cudaGetSymbolAddress(&pg, g_g);
    float* h    = (float*)ph;
    float* uvqk = (float*)puvqk;
    float* attn = (float*)pattn;
    float* g    = (float*)pg;

    const int smem_attn = 3 * 64 * APAD * sizeof(float);  // 52224 B
    cudaFuncSetAttribute(attn_k, cudaFuncAttributeMaxDynamicSharedMemorySize, smem_attn);

    // h = rms_norm(x, in_norm_w)
    rmsnorm_k<<<MROWS, 256>>>(x, in_nw, h);

    for (int l = 0; l < LL; l++) {
        const float* wl  = uvqk_w + (size_t)l * DD * FOURD;
        const float* bl  = uvqk_b + (size_t)l * FOURD;
        const float* gwl = gate_w + (size_t)l * DD;
        const float* owl = out_w + (size_t)l * DD * DD;
        const float* obl = out_b + (size_t)l * DD;

        // uvqk = h @ W + b
        sgemm_k<false><<<dim3(FOURD / 128, MROWS / 128), 256>>>(
            MROWS, FOURD, DD, h, wl, bl, nullptr, uvqk);
        // silu(u), rope(q,k)
        rope_silu_k<<<MROWS, 128>>>(uvqk, td, pos_ids);
        // attention
        attn_k<<<dim3(SS / 64, BB * HH), 256, smem_attn>>>(uvqk, attn);
        // gated = rms_norm(attn, gate_w) * u
        rmsgate_k<<<MROWS, 256>>>(attn, gwl, uvqk, g);
        // h = h + g @ out_w + out_b  (in-place safe: each elem read once in epilogue)
        sgemm_k<true><<<dim3(DD / 128, MROWS / 128), 256>>>(
            MROWS, DD, DD, g, owl, obl, h, h);
    }

    // out = rms_norm(h, last_norm_w)
    rmsnorm_k<<<MROWS, 256>>>(h, last_nw, out);
}

// round 3
// speedup vs baseline: 1.6078x; 1.6078x over previous
#include <cuda_runtime.h>
#include <cuda_bf16.h>
#include <math.h>
#include <stdint.h>

// Problem constants
#define BB 2
#define SS 2048
#define DD 1024
#define HH 16
#define HD 64
#define LL 4
#define MROWS (BB*SS)          // 4096
#define FOURD (4*DD)           // 4096

// ---------------------------------------------------------------------------
// Scratch (device globals; no allocation allowed)
// ---------------------------------------------------------------------------
__device__ float g_h[MROWS * DD];        // hidden state
__device__ float g_uvqk[MROWS * FOURD];  // uvqk projection
__device__ float g_attn[MROWS * DD];     // attention output
__device__ float g_g[MROWS * DD];        // gated

__device__ __nv_bfloat16 g_wqk_hi[LL * FOURD * DD];  // uvqk_w^T split, [L][N=4D][K=D]
__device__ __nv_bfloat16 g_wqk_lo[LL * FOURD * DD];
__device__ __nv_bfloat16 g_wo_hi[LL * DD * DD];      // out_w^T split, [L][N=D][K=D]
__device__ __nv_bfloat16 g_wo_lo[LL * DD * DD];
__device__ __nv_bfloat16 g_ahi[MROWS * DD];          // activation split
__device__ __nv_bfloat16 g_alo[MROWS * DD];

// ---------------------------------------------------------------------------
// PTX helpers (legacy tensor-core path: valid under compute_103 PTX)
// ---------------------------------------------------------------------------
__device__ __forceinline__ uint32_t smem_u32(const void* p) {
    uint32_t a;
    asm("{ .reg .u64 t; cvta.to.shared.u64 t, %1; cvt.u32.u64 %0, t; }" : "=r"(a) : "l"(p));
    return a;
}
__device__ __forceinline__ void cp_async16(uint32_t dst, const void* src) {
    asm volatile("cp.async.cg.shared.global [%0], [%1], 16;" :: "r"(dst), "l"(src) : "memory");
}
#define CP_COMMIT()  asm volatile("cp.async.commit_group;" ::: "memory")
#define CP_WAIT0()   asm volatile("cp.async.wait_group 0;" ::: "memory")
#define CP_WAIT1()   asm volatile("cp.async.wait_group 1;" ::: "memory")

__device__ __forceinline__ void ldsm4(uint32_t* r, uint32_t addr) {
    asm volatile("ldmatrix.sync.aligned.m8n8.x4.shared.b16 {%0,%1,%2,%3}, [%4];"
                 : "=r"(r[0]), "=r"(r[1]), "=r"(r[2]), "=r"(r[3]) : "r"(addr));
}
__device__ __forceinline__ void mma_bf16(float* c, const uint32_t* a, const uint32_t* b) {
    asm volatile("mma.sync.aligned.m16n8k16.row.col.f32.bf16.bf16.f32 "
                 "{%0,%1,%2,%3}, {%4,%5,%6,%7}, {%8,%9}, {%0,%1,%2,%3};"
                 : "+f"(c[0]), "+f"(c[1]), "+f"(c[2]), "+f"(c[3])
                 : "r"(a[0]), "r"(a[1]), "r"(a[2]), "r"(a[3]), "r"(b[0]), "r"(b[1]));
}

// ---------------------------------------------------------------------------
// Weight convert+transpose+split: W[K,N] fp32 -> Thi/Tlo [N,K] bf16 (layer z)
// ---------------------------------------------------------------------------
__global__ void wconv_k(const float* __restrict__ W, __nv_bfloat16* __restrict__ Thi,
                        __nv_bfloat16* __restrict__ Tlo, int K, int N) {
    __shared__ float t[32][33];
    int l = blockIdx.z;
    const float* Wl = W + (size_t)l * K * N;
    __nv_bfloat16* Hl = Thi + (size_t)l * K * N;
    __nv_bfloat16* Ll = Tlo + (size_t)l * K * N;
    int n0 = blockIdx.x * 32, k0 = blockIdx.y * 32;
    int tx = threadIdx.x, ty = threadIdx.y;
    #pragma unroll
    for (int i = 0; i < 32; i += 8)
        t[ty + i][tx] = Wl[(size_t)(k0 + ty + i) * N + n0 + tx];
    __syncthreads();
    #pragma unroll
    for (int i = 0; i < 32; i += 8) {
        float v = t[tx][ty + i];
        __nv_bfloat16 hi = __float2bfloat16(v);
        __nv_bfloat16 lo = __float2bfloat16(v - __bfloat162float(hi));
        size_t o = (size_t)(n0 + ty + i) * K + k0 + tx;
        Hl[o] = hi;
        Ll[o] = lo;
    }
}

// Activation split: x fp32 -> hi/lo bf16
__global__ void aconv_k(const float* __restrict__ x, __nv_bfloat16* __restrict__ hi,
                        __nv_bfloat16* __restrict__ lo, int n) {
    int i = blockIdx.x * blockDim.x + threadIdx.x;
    if (i < n) {
        float v = x[i];
        __nv_bfloat16 h = __float2bfloat16(v);
        hi[i] = h;
        lo[i] = __float2bfloat16(v - __bfloat162float(h));
    }
}

// ---------------------------------------------------------------------------
// mma.sync bf16x3 GEMM: C[M,N] = Ahi*Bhi + Ahi*Blo + Alo*Bhi (+bias, +res)
// A*: [M,K] bf16 row-major; B*: [N,K] bf16 row-major (pre-transposed weights)
// 128x128 tile/CTA, BK=32, cp.async double buffer, 8 warps @ 64x32 warp tile.
// SMEM rows padded to 40 elems (80B) -> ldmatrix conflict-free.
// ---------------------------------------------------------------------------
#define ROWE 40
#define ARR_B (128 * ROWE * 2)   // 10240 B per tile array
#define STG_B (4 * ARR_B)        // 40960 B per stage (Ahi,Alo,Bhi,Blo)
#define GSMEM (2 * STG_B)        // 81920 B

template<bool ADD_RES>
__global__ __launch_bounds__(256, 1)
void mmagemm_k(int N, int K,
               const __nv_bfloat16* __restrict__ Ahi, const __nv_bfloat16* __restrict__ Alo,
               const __nv_bfloat16* __restrict__ Bhi, const __nv_bfloat16* __restrict__ Blo,
               const float* __restrict__ bias, const float* __restrict__ res,
               float* __restrict__ C) {
    extern __shared__ char dynsm[];
    const uint32_t sb = smem_u32(dynsm);
    const int tid = threadIdx.x;
    const int lane = tid & 31, wid = tid >> 5;
    const int warpM = (wid >> 2) * 64;   // 0 or 64
    const int warpN = (wid & 3) * 32;    // 0..96
    const int m0 = blockIdx.y * 128;
    const int n0 = blockIdx.x * 128;
    const int nk = K / 32;

    const __nv_bfloat16* srcs[4] = {
        Ahi + (size_t)m0 * K, Alo + (size_t)m0 * K,
        Bhi + (size_t)n0 * K, Blo + (size_t)n0 * K };

    const int lrow = tid >> 2;       // 0..63
    const int lch  = tid & 3;        // chunk 0..3 (16B each = 8 elems)

    auto load_stage = [&](int stage, int kc) {
        const int k0 = kc * 32;
        const uint32_t dbase = sb + stage * STG_B;
        #pragma unroll
        for (int j = 0; j < 8; j++) {
            const int arr = j >> 1;
            const int row = lrow + ((j & 1) ? 64 : 0);
            uint32_t dst = dbase + arr * ARR_B + row * (ROWE * 2) + lch * 16;
            const __nv_bfloat16* src = srcs[arr] + (size_t)row * K + k0 + lch * 8;
            cp_async16(dst, src);
        }
        CP_COMMIT();
    };

    // fragment smem offsets (lane-dependent, stage/array-independent parts)
    const uint32_t aoff = (uint32_t)(warpM + (lane & 15)) * (ROWE * 2) + (lane >> 4) * 16;
    const uint32_t boff = (uint32_t)(warpN + (lane >> 4) * 8 + (lane & 7)) * (ROWE * 2)
                          + ((lane >> 3) & 1) * 16;

    float acc[4][4][4] = {};

    load_stage(0, 0);

    for (int kc = 0; kc < nk; kc++) {
        if (kc + 1 < nk) {
            load_stage((kc + 1) & 1, kc + 1);
            CP_WAIT1();
        } else {
            CP_WAIT0();
        }
        __syncthreads();

        const uint32_t stb = sb + (kc & 1) * STG_B;
        #pragma unroll
        for (int ks = 0; ks < 2; ks++) {
            const uint32_t ko = ks * 32;  // 16 elems * 2B
            uint32_t ah[4][4], al[4][4];
            #pragma unroll
            for (int mt = 0; mt < 4; mt++) {
                uint32_t a = stb + aoff + mt * (16 * ROWE * 2) + ko;
                ldsm4(ah[mt], a);
                ldsm4(al[mt], a + ARR_B);
            }
            uint32_t bh[2][4], bl[2][4];
            #pragma unroll
            for (int p = 0; p < 2; p++) {
                uint32_t b = stb + 2 * ARR_B + boff + p * (16 * ROWE * 2) + ko;
                ldsm4(bh[p], b);
                ldsm4(bl[p], b + ARR_B);
            }
            #pragma unroll
            for (int mt = 0; mt < 4; mt++) {
                #pragma unroll
                for (int nt = 0; nt < 4; nt++) {
                    const uint32_t* Bh = &bh[nt >> 1][(nt & 1) * 2];
                    const uint32_t* Bl = &bl[nt >> 1][(nt & 1) * 2];
                    mma_bf16(acc[mt][nt], ah[mt], Bh);
                    mma_bf16(acc[mt][nt], ah[mt], Bl);
                    mma_bf16(acc[mt][nt], al[mt], Bh);
                }
            }
        }
        __syncthreads();
    }

    // epilogue: fragment (m16n8): c0,c1 -> (row, col/col+1), c2,c3 -> (row+8, ..)
    const int frow = lane >> 2;
    const int fcol = (lane & 3) * 2;
    #pragma unroll
    for (int mt = 0; mt < 4; mt++) {
        const int m = m0 + warpM + mt * 16 + frow;
        #pragma unroll
        for (int nt = 0; nt < 4; nt++) {
            const int n = n0 + warpN + nt * 8 + fcol;
            const float* a = acc[mt][nt];
            float2 bv = *reinterpret_cast<const float2*>(bias + n);
            float2 o0 = { a[0] + bv.x, a[1] + bv.y };
            float2 o1 = { a[2] + bv.x, a[3] + bv.y };
            if (ADD_RES) {
                float2 r0 = *reinterpret_cast<const float2*>(res + (size_t)m * N + n);
                float2 r1 = *reinterpret_cast<const float2*>(res + (size_t)(m + 8) * N + n);
                o0.x += r0.x; o0.y += r0.y;
                o1.x += r1.x; o1.y += r1.y;
            }
            *reinterpret_cast<float2*>(C + (size_t)m * N + n) = o0;
            *reinterpret_cast<float2*>(C + (size_t)(m + 8) * N + n) = o1;
        }
    }
}

// ---------------------------------------------------------------------------
// block reduce
// ---------------------------------------------------------------------------
__device__ __forceinline__ float blockReduceSum(float v) {
    __shared__ float red[8];
    int lane = threadIdx.x & 31, wid = threadIdx.x >> 5;
    #pragma unroll
    for (int o = 16; o; o >>= 1) v += __shfl_down_sync(0xFFFFFFFFu, v, o);
    if (lane == 0) red[wid] = v;
    __syncthreads();
    float r = 0.f;
    if (threadIdx.x < (blockDim.x >> 5)) r = red[threadIdx.x];
    if (wid == 0) {
        #pragma unroll
        for (int o = 4; o; o >>= 1) r += __shfl_down_sync(0xFFFFFFFFu, r, o);
        if (lane == 0) red[0] = r;
    }
    __syncthreads();
    return red[0];
}

__global__ void rmsnorm_k(const float* __restrict__ in, const float* __restrict__ w,
                          float* __restrict__ out) {
    int row = blockIdx.x;
    const float* x = in + (size_t)row * DD;
    float ss = 0.f;
    for (int i = threadIdx.x; i < DD; i += blockDim.x) { float v = x[i]; ss += v * v; }
    float tot = blockReduceSum(ss);
    float inv = rsqrtf(tot / (float)DD + 1e-6f);
    for (int i = threadIdx.x; i < DD; i += blockDim.x)
        out[(size_t)row * DD + i] = w[i] * x[i] * inv;
}

// ---------------------------------------------------------------------------
// RoPE (q,k) + SiLU (u) in-place on uvqk. One block per token.
// ---------------------------------------------------------------------------
__global__ void rope_silu_k(float* __restrict__ uvqk,
                            const float* __restrict__ td,
                            const int* __restrict__ pos_ids) {
    int t = blockIdx.x;
    __shared__ float cs[32], sn[32];
    if (threadIdx.x < 32) {
        float p = (float)pos_ids[t] + 0.1f * logf(td[t] + 1.0f);
        float invf = expf(-logf(10000.0f) * (float)threadIdx.x / 32.0f);
        float f = p * invf;
        cs[threadIdx.x] = cosf(f);
        sn[threadIdx.x] = sinf(f);
    }
    __syncthreads();
    float* row = uvqk + (size_t)t * FOURD;
    for (int i = threadIdx.x; i < DD; i += blockDim.x) {
        float v = row[i];
        row[i] = v / (1.0f + expf(-v));
    }
    for (int p = threadIdx.x; p < HH * 32; p += blockDim.x) {
        int hh = p >> 5, i = p & 31;
        int base = 2 * DD + hh * HD + i;
        float c = cs[i], s = sn[i];
        float q1 = row[base], q2 = row[base + 32];
        row[base]      = q1 * c - q2 * s;
        row[base + 32] = q2 * c + q1 * s;
        int base2 = base + DD;
        float k1 = row[base2], k2 = row[base2 + 32];
        row[base2]      = k1 * c - k2 * s;
        row[base2 + 32] = k2 * c + k1 * s;
    }
}

// ---------------------------------------------------------------------------
// Fused causal SiLU attention (fp32). grid=(S/64, B*H), 256 threads.
// ---------------------------------------------------------------------------
#define APAD 68
__global__ __launch_bounds__(256)
void attn_k(const float* __restrict__ uvqk, float* __restrict__ out) {
    extern __shared__ float sm[];
    float* qs  = sm;
    float* kss = sm + 64 * APAD;
    float* vs  = sm + 2 * 64 * APAD;

    int qt = blockIdx.x, bh = blockIdx.y;
    int b = bh >> 4, h = bh & 15;
    int q0 = qt * 64;
    int tid = threadIdx.x;
    int ry = (tid >> 4) * 4;
    int cx = (tid & 15) * 4;

    const size_t rstr = FOURD;
    const float* qbase = uvqk + (size_t)(b * SS) * rstr + 2 * DD + h * HD;
    const float* kbase = uvqk + (size_t)(b * SS) * rstr + 3 * DD + h * HD;
    const float* vbase = uvqk + (size_t)(b * SS) * rstr + 1 * DD + h * HD;

    #pragma unroll
    for (int it = 0; it < 4; it++) {
        int r = (tid >> 4) + it * 16;
        int c4 = (tid & 15) * 4;
        float4 v = *reinterpret_cast<const float4*>(qbase + (size_t)(q0 + r) * rstr + c4);
        *reinterpret_cast<float4*>(&qs[r * APAD + c4]) = v;
    }

    float outacc[4][4] = {};

    for (int kt = 0; kt <= qt; kt++) {
        int k0 = kt * 64;
        __syncthreads();
        #pragma unroll
        for (int it = 0; it < 4; it++) {
            int r = (tid >> 4) + it * 16;
            int c4 = (tid & 15) * 4;
            float4 kv = *reinterpret_cast<const float4*>(kbase + (size_t)(k0 + r) * rstr + c4);
            kss[(c4 + 0) * APAD + r] = kv.x;
            kss[(c4 + 1) * APAD + r] = kv.y;
            kss[(c4 + 2) * APAD + r] = kv.z;
            kss[(c4 + 3) * APAD + r] = kv.w;
            float4 vv = *reinterpret_cast<const float4*>(vbase + (size_t)(k0 + r) * rstr + c4);
            *reinterpret_cast<float4*>(&vs[r * APAD + c4]) = vv;
        }
        __syncthreads();

        float s[4][4] = {};
        #pragma unroll 8
        for (int d = 0; d < 64; d++) {
            float qf[4], kf[4];
            #pragma unroll
            for (int i = 0; i < 4; i++) qf[i] = qs[(ry + i) * APAD + d];
            #pragma unroll
            for (int j = 0; j < 4; j++) kf[j] = kss[d * APAD + cx + j];
            #pragma unroll
            for (int i = 0; i < 4; i++)
                #pragma unroll
                for (int j = 0; j < 4; j++) s[i][j] += qf[i] * kf[j];
        }
        float w[4][4];
        #pragma unroll
        for (int i = 0; i < 4; i++)
            #pragma unroll
            for (int j = 0; j < 4; j++) {
                float v = s[i][j] * 0.125f;
                v = v / (1.0f + expf(-v));
                if (k0 + cx + j > q0 + ry + i) v = 0.0f;
                w[i][j] = v;
            }
        __syncthreads();
        #pragma unroll
        for (int i = 0; i < 4; i++)
            #pragma unroll
            for (int j = 0; j < 4; j++)
                kss[(ry + i) * APAD + cx + j] = w[i][j];
        __syncthreads();

        #pragma unroll 8
        for (int j = 0; j < 64; j++) {
            float sf[4], vf[4];
            #pragma unroll
            for (int i = 0; i < 4; i++) sf[i] = kss[(ry + i) * APAD + j];
            #pragma unroll
            for (int jj = 0; jj < 4; jj++) vf[jj] = vs[j * APAD + cx + jj];
            #pragma unroll
            for (int i = 0; i < 4; i++)
                #pragma unroll
                for (int jj = 0; jj < 4; jj++) outacc[i][jj] += sf[i] * vf[jj];
        }
    }

    #pragma unroll
    for (int i = 0; i < 4; i++) {
        size_t o = (size_t)(b * SS + q0 + ry + i) * DD + h * HD + cx;
        float4 v;
        v.x = outacc[i][0]; v.y = outacc[i][1]; v.z = outacc[i][2]; v.w = outacc[i][3];
        *reinterpret_cast<float4*>(out + o) = v;
    }
}

// ---------------------------------------------------------------------------
// gated = rms_norm(attn, gate_w) * u
// ---------------------------------------------------------------------------
__global__ void rmsgate_k(const float* __restrict__ attn, const float* __restrict__ gw,
                          const float* __restrict__ uvqk, float* __restrict__ g) {
    int row = blockIdx.x;
    const float* x = attn + (size_t)row * DD;
    const float* u = uvqk + (size_t)row * FOURD;
    float ss = 0.f;
    for (int i = threadIdx.x; i < DD; i += blockDim.x) { float v = x[i]; ss += v * v; }
    float tot = blockReduceSum(ss);
    float inv = rsqrtf(tot / (float)DD + 1e-6f);
    for (int i = threadIdx.x; i < DD; i += blockDim.x)
        g[(size_t)row * DD + i] = gw[i] * x[i] * inv * u[i];
}

// ---------------------------------------------------------------------------
// kernel_launch
// ---------------------------------------------------------------------------
extern "C" void kernel_launch(void* const* d_in, const int* in_sizes, int n_in,
                              void* d_out, int out_size) {
    const float* x        = (const float*)d_in[0];
    const float* td       = (const float*)d_in[1];
    // d_in[2] = attn_mask: structurally tril(ones) -> causal mask applied in-kernel
    const float* uvqk_w   = (const float*)d_in[3];
    const float* uvqk_b   = (const float*)d_in[4];
    const float* gate_w   = (const float*)d_in[5];
    const float* out_w    = (const float*)d_in[6];
    const float* out_b    = (const float*)d_in[7];
    const float* in_nw    = (const float*)d_in[8];
    const float* last_nw  = (const float*)d_in[9];
    const int*   pos_ids  = (const int*)d_in[10];
    float* out = (float*)d_out;

    void *ph, *puvqk, *pattn, *pg;
    void *pwqh, *pwql, *pwoh, *pwol, *pahi, *palo;
    cudaGetSymbolAddress(&ph, g_h);
    cudaGetSymbolAddress(&puvqk, g_uvqk);
    cudaGetSymbolAddress(&pattn, g_attn);
    cudaGetSymbolAddress(&pg, g_g);
    cudaGetSymbolAddress(&pwqh, g_wqk_hi);
    cudaGetSymbolAddress(&pwql, g_wqk_lo);
    cudaGetSymbolAddress(&pwoh, g_wo_hi);
    cudaGetSymbolAddress(&pwol, g_wo_lo);
    cudaGetSymbolAddress(&pahi, g_ahi);
    cudaGetSymbolAddress(&palo, g_alo);
    float* h    = (float*)ph;
    float* uvqk = (float*)puvqk;
    float* attn = (float*)pattn;
    float* g    = (float*)pg;
    __nv_bfloat16* wqh = (__nv_bfloat16*)pwqh;
    __nv_bfloat16* wql = (__nv_bfloat16*)pwql;
    __nv_bfloat16* woh = (__nv_bfloat16*)pwoh;
    __nv_bfloat16* wol = (__nv_bfloat16*)pwol;
    __nv_bfloat16* ahi = (__nv_bfloat16*)pahi;
    __nv_bfloat16* alo = (__nv_bfloat16*)palo;

    const int smem_attn = 3 * 64 * APAD * sizeof(float);
    cudaFuncSetAttribute(attn_k, cudaFuncAttributeMaxDynamicSharedMemorySize, smem_attn);
    cudaFuncSetAttribute(mmagemm_k<false>, cudaFuncAttributeMaxDynamicSharedMemorySize, GSMEM);
    cudaFuncSetAttribute(mmagemm_k<true>,  cudaFuncAttributeMaxDynamicSharedMemorySize, GSMEM);

    // weight convert (transpose + bf16 split), all layers
    wconv_k<<<dim3(FOURD / 32, DD / 32, LL), dim3(32, 8)>>>(uvqk_w, wqh, wql, DD, FOURD);
    wconv_k<<<dim3(DD / 32, DD / 32, LL), dim3(32, 8)>>>(out_w, woh, wol, DD, DD);

    // h = rms_norm(x, in_norm_w)
    rmsnorm_k<<<MROWS, 256>>>(x, in_nw, h);

    for (int l = 0; l < LL; l++) {
        const __nv_bfloat16* wqhl = wqh + (size_t)l * FOURD * DD;
        const __nv_bfloat16* wqll = wql + (size_t)l * FOURD * DD;
        const __nv_bfloat16* wohl = woh + (size_t)l * DD * DD;
        const __nv_bfloat16* woll = wol + (size_t)l * DD * DD;
        const float* bl  = uvqk_b + (size_t)l * FOURD;
        const float* gwl = gate_w + (size_t)l * DD;
        const float* obl = out_b + (size_t)l * DD;

        // uvqk = h @ W + b   (tensor cores, bf16x3)
        aconv_k<<<(MROWS * DD + 255) / 256, 256>>>(h, ahi, alo, MROWS * DD);
        mmagemm_k<false><<<dim3(FOURD / 128, MROWS / 128), 256, GSMEM>>>(
            FOURD, DD, ahi, alo, wqhl, wqll, bl, nullptr, uvqk);
        // silu(u), rope(q,k)
        rope_silu_k<<<MROWS, 128>>>(uvqk, td, pos_ids);
        // attention (fp32)
        attn_k<<<dim3(SS / 64, BB * HH), 256, smem_attn>>>(uvqk, attn);
        // gated = rms_norm(attn, gate_w) * u
        rmsgate_k<<<MROWS, 256>>>(attn, gwl, uvqk, g);
        // h = h + g @ out_w + out_b  (tensor cores, bf16x3)
        aconv_k<<<(MROWS * DD + 255) / 256, 256>>>(g, ahi, alo, MROWS * DD);
        mmagemm_k<true><<<dim3(DD / 128, MROWS / 128), 256, GSMEM>>>(
            DD, DD, ahi, alo, wohl, woll, obl, h, h);
    }

    rmsnorm_k<<<MROWS, 256>>>(h, last_nw, out);
}

// round 4
// speedup vs baseline: 2.3275x; 1.4476x over previous
#include <cuda_runtime.h>
#include <cuda_bf16.h>
#include <math.h>
#include <stdint.h>

// Problem constants
#define BB 2
#define SS 2048
#define DD 1024
#define HH 16
#define HD 64
#define LL 4
#define MROWS (BB*SS)          // 4096
#define FOURD (4*DD)           // 4096

// ---------------------------------------------------------------------------
// Scratch (device globals; no allocation allowed)
// ---------------------------------------------------------------------------
__device__ float g_h[MROWS * DD];        // hidden state
__device__ float g_uvqk[MROWS * FOURD];  // uvqk projection (u slot holds silu(u))
__device__ float g_attn[MROWS * DD];     // attention output

__device__ __nv_bfloat16 g_wqk_hi[LL * FOURD * DD];  // uvqk_w^T split, [L][N=4D][K=D]
__device__ __nv_bfloat16 g_wqk_lo[LL * FOURD * DD];
__device__ __nv_bfloat16 g_wo_hi[LL * DD * DD];      // out_w^T split, [L][N=D][K=D]
__device__ __nv_bfloat16 g_wo_lo[LL * DD * DD];
__device__ __nv_bfloat16 g_ahi[MROWS * DD];          // h split (GEMM A input)
__device__ __nv_bfloat16 g_alo[MROWS * DD];
__device__ __nv_bfloat16 g_ghi[MROWS * DD];          // gated split (GEMM A input)
__device__ __nv_bfloat16 g_glo[MROWS * DD];
// q/k/v splits in [b,h,s,d] layout
__device__ __nv_bfloat16 g_qhi[MROWS * DD];
__device__ __nv_bfloat16 g_qlo[MROWS * DD];
__device__ __nv_bfloat16 g_khi[MROWS * DD];
__device__ __nv_bfloat16 g_klo[MROWS * DD];
__device__ __nv_bfloat16 g_vhi[MROWS * DD];
__device__ __nv_bfloat16 g_vlo[MROWS * DD];

// ---------------------------------------------------------------------------
// PTX helpers (legacy tensor-core path: valid under compute_103 PTX)
// ---------------------------------------------------------------------------
__device__ __forceinline__ uint32_t smem_u32(const void* p) {
    uint32_t a;
    asm("{ .reg .u64 t; cvta.to.shared.u64 t, %1; cvt.u32.u64 %0, t; }" : "=r"(a) : "l"(p));
    return a;
}
__device__ __forceinline__ void cp_async16(uint32_t dst, const void* src) {
    asm volatile("cp.async.cg.shared.global [%0], [%1], 16;" :: "r"(dst), "l"(src) : "memory");
}
#define CP_COMMIT()  asm volatile("cp.async.commit_group;" ::: "memory")
#define CP_WAIT0()   asm volatile("cp.async.wait_group 0;" ::: "memory")
#define CP_WAIT1()   asm volatile("cp.async.wait_group 1;" ::: "memory")

__device__ __forceinline__ void ldsm4(uint32_t* r, uint32_t addr) {
    asm volatile("ldmatrix.sync.aligned.m8n8.x4.shared.b16 {%0,%1,%2,%3}, [%4];"
                 : "=r"(r[0]), "=r"(r[1]), "=r"(r[2]), "=r"(r[3]) : "r"(addr));
}
__device__ __forceinline__ void ldsm4t(uint32_t* r, uint32_t addr) {
    asm volatile("ldmatrix.sync.aligned.m8n8.x4.trans.shared.b16 {%0,%1,%2,%3}, [%4];"
                 : "=r"(r[0]), "=r"(r[1]), "=r"(r[2]), "=r"(r[3]) : "r"(addr));
}
__device__ __forceinline__ void mma_bf16(float* c, const uint32_t* a, const uint32_t* b) {
    asm volatile("mma.sync.aligned.m16n8k16.row.col.f32.bf16.bf16.f32 "
                 "{%0,%1,%2,%3}, {%4,%5,%6,%7}, {%8,%9}, {%0,%1,%2,%3};"
                 : "+f"(c[0]), "+f"(c[1]), "+f"(c[2]), "+f"(c[3])
                 : "r"(a[0]), "r"(a[1]), "r"(a[2]), "r"(a[3]), "r"(b[0]), "r"(b[1]));
}
// pack two fp32 into bf16x2 reg: lo goes to bits[15:0]
__device__ __forceinline__ uint32_t packbf(float lo, float hi) {
    uint32_t r;
    asm("cvt.rn.bf16x2.f32 %0, %1, %2;" : "=r"(r) : "f"(hi), "f"(lo));
    return r;
}

// ---------------------------------------------------------------------------
// Weight convert+transpose+split: W[K,N] fp32 -> Thi/Tlo [N,K] bf16 (layer z)
// ---------------------------------------------------------------------------
__global__ void wconv_k(const float* __restrict__ W, __nv_bfloat16* __restrict__ Thi,
                        __nv_bfloat16* __restrict__ Tlo, int K, int N) {
    __shared__ float t[32][33];
    int l = blockIdx.z;
    const float* Wl = W + (size_t)l * K * N;
    __nv_bfloat16* Hl = Thi + (size_t)l * K * N;
    __nv_bfloat16* Ll = Tlo + (size_t)l * K * N;
    int n0 = blockIdx.x * 32, k0 = blockIdx.y * 32;
    int tx = threadIdx.x, ty = threadIdx.y;
    #pragma unroll
    for (int i = 0; i < 32; i += 8)
        t[ty + i][tx] = Wl[(size_t)(k0 + ty + i) * N + n0 + tx];
    __syncthreads();
    #pragma unroll
    for (int i = 0; i < 32; i += 8) {
        float v = t[tx][ty + i];
        __nv_bfloat16 hi = __float2bfloat16(v);
        __nv_bfloat16 lo = __float2bfloat16(v - __bfloat162float(hi));
        size_t o = (size_t)(n0 + ty + i) * K + k0 + tx;
        Hl[o] = hi;
        Ll[o] = lo;
    }
}

// ---------------------------------------------------------------------------
// mma.sync bf16x3 GEMM: C[M,N] = Ahi*Bhi + Ahi*Blo + Alo*Bhi (+bias, +res)
// Optional SPLIT: also emit bf16 hi/lo of C (feeds next GEMM).
// ---------------------------------------------------------------------------
#define ROWE 40
#define ARR_B (128 * ROWE * 2)   // 10240 B per tile array
#define STG_B (4 * ARR_B)        // 40960 B per stage (Ahi,Alo,Bhi,Blo)
#define GSMEM (2 * STG_B)        // 81920 B

template<bool ADD_RES, bool SPLIT>
__global__ __launch_bounds__(256, 1)
void mmagemm_k(int N, int K,
               const __nv_bfloat16* __restrict__ Ahi, const __nv_bfloat16* __restrict__ Alo,
               const __nv_bfloat16* __restrict__ Bhi, const __nv_bfloat16* __restrict__ Blo,
               const float* __restrict__ bias, const float* __restrict__ res,
               float* __restrict__ C,
               __nv_bfloat16* __restrict__ Chi, __nv_bfloat16* __restrict__ Clo) {
    extern __shared__ char dynsm[];
    const uint32_t sb = smem_u32(dynsm);
    const int tid = threadIdx.x;
    const int lane = tid & 31, wid = tid >> 5;
    const int warpM = (wid >> 2) * 64;
    const int warpN = (wid & 3) * 32;
    const int m0 = blockIdx.y * 128;
    const int n0 = blockIdx.x * 128;
    const int nk = K / 32;

    const __nv_bfloat16* srcs[4] = {
        Ahi + (size_t)m0 * K, Alo + (size_t)m0 * K,
        Bhi + (size_t)n0 * K, Blo + (size_t)n0 * K };

    const int lrow = tid >> 2;
    const int lch  = tid & 3;

    auto load_stage = [&](int stage, int kc) {
        const int k0 = kc * 32;
        const uint32_t dbase = sb + stage * STG_B;
        #pragma unroll
        for (int j = 0; j < 8; j++) {
            const int arr = j >> 1;
            const int row = lrow + ((j & 1) ? 64 : 0);
            uint32_t dst = dbase + arr * ARR_B + row * (ROWE * 2) + lch * 16;
            const __nv_bfloat16* src = srcs[arr] + (size_t)row * K + k0 + lch * 8;
            cp_async16(dst, src);
        }
        CP_COMMIT();
    };

    const uint32_t aoff = (uint32_t)(warpM + (lane & 15)) * (ROWE * 2) + (lane >> 4) * 16;
    const uint32_t boff = (uint32_t)(warpN + (lane >> 4) * 8 + (lane & 7)) * (ROWE * 2)
                          + ((lane >> 3) & 1) * 16;

    float acc[4][4][4] = {};

    load_stage(0, 0);

    for (int kc = 0; kc < nk; kc++) {
        if (kc + 1 < nk) {
            load_stage((kc + 1) & 1, kc + 1);
            CP_WAIT1();
        } else {
            CP_WAIT0();
        }
        __syncthreads();

        const uint32_t stb = sb + (kc & 1) * STG_B;
        #pragma unroll
        for (int ks = 0; ks < 2; ks++) {
            const uint32_t ko = ks * 32;
            uint32_t ah[4][4], al[4][4];
            #pragma unroll
            for (int mt = 0; mt < 4; mt++) {
                uint32_t a = stb + aoff + mt * (16 * ROWE * 2) + ko;
                ldsm4(ah[mt], a);
                ldsm4(al[mt], a + ARR_B);
            }
            uint32_t bh[2][4], bl[2][4];
            #pragma unroll
            for (int p = 0; p < 2; p++) {
                uint32_t b = stb + 2 * ARR_B + boff + p * (16 * ROWE * 2) + ko;
                ldsm4(bh[p], b);
                ldsm4(bl[p], b + ARR_B);
            }
            #pragma unroll
            for (int mt = 0; mt < 4; mt++) {
                #pragma unroll
                for (int nt = 0; nt < 4; nt++) {
                    const uint32_t* Bh = &bh[nt >> 1][(nt & 1) * 2];
                    const uint32_t* Bl = &bl[nt >> 1][(nt & 1) * 2];
                    mma_bf16(acc[mt][nt], ah[mt], Bh);
                    mma_bf16(acc[mt][nt], ah[mt], Bl);
                    mma_bf16(acc[mt][nt], al[mt], Bh);
                }
            }
        }
        __syncthreads();
    }

    const int frow = lane >> 2;
    const int fcol = (lane & 3) * 2;
    #pragma unroll
    for (int mt = 0; mt < 4; mt++) {
        const int m = m0 + warpM + mt * 16 + frow;
        #pragma unroll
        for (int nt = 0; nt < 4; nt++) {
            const int n = n0 + warpN + nt * 8 + fcol;
            const float* a = acc[mt][nt];
            float2 bv = *reinterpret_cast<const float2*>(bias + n);
            float2 o0 = { a[0] + bv.x, a[1] + bv.y };
            float2 o1 = { a[2] + bv.x, a[3] + bv.y };
            if (ADD_RES) {
                float2 r0 = *reinterpret_cast<const float2*>(res + (size_t)m * N + n);
                float2 r1 = *reinterpret_cast<const float2*>(res + (size_t)(m + 8) * N + n);
                o0.x += r0.x; o0.y += r0.y;
                o1.x += r1.x; o1.y += r1.y;
            }
            *reinterpret_cast<float2*>(C + (size_t)m * N + n) = o0;
            *reinterpret_cast<float2*>(C + (size_t)(m + 8) * N + n) = o1;
            if (SPLIT) {
                __nv_bfloat162 h0, h1, l0, l1;
                h0.x = __float2bfloat16(o0.x); h0.y = __float2bfloat16(o0.y);
                h1.x = __float2bfloat16(o1.x); h1.y = __float2bfloat16(o1.y);
                l0.x = __float2bfloat16(o0.x - __bfloat162float(h0.x));
                l0.y = __float2bfloat16(o0.y - __bfloat162float(h0.y));
                l1.x = __float2bfloat16(o1.x - __bfloat162float(h1.x));
                l1.y = __float2bfloat16(o1.y - __bfloat162float(h1.y));
                *reinterpret_cast<__nv_bfloat162*>(Chi + (size_t)m * N + n) = h0;
                *reinterpret_cast<__nv_bfloat162*>(Chi + (size_t)(m + 8) * N + n) = h1;
                *reinterpret_cast<__nv_bfloat162*>(Clo + (size_t)m * N + n) = l0;
                *reinterpret_cast<__nv_bfloat162*>(Clo + (size_t)(m + 8) * N + n) = l1;
            }
        }
    }
}

// ---------------------------------------------------------------------------
// block reduce
// ---------------------------------------------------------------------------
__device__ __forceinline__ float blockReduceSum(float v) {
    __shared__ float red[8];
    int lane = threadIdx.x & 31, wid = threadIdx.x >> 5;
    #pragma unroll
    for (int o = 16; o; o >>= 1) v += __shfl_down_sync(0xFFFFFFFFu, v, o);
    if (lane == 0) red[wid] = v;
    __syncthreads();
    float r = 0.f;
    if (threadIdx.x < (blockDim.x >> 5)) r = red[threadIdx.x];
    if (wid == 0) {
        #pragma unroll
        for (int o = 4; o; o >>= 1) r += __shfl_down_sync(0xFFFFFFFFu, r, o);
        if (lane == 0) red[0] = r;
    }
    __syncthreads();
    return red[0];
}

// RMS norm; optionally also emit bf16 hi/lo split of output
template<bool SPLIT>
__global__ void rmsnorm_k(const float* __restrict__ in, const float* __restrict__ w,
                          float* __restrict__ out,
                          __nv_bfloat16* __restrict__ ohi, __nv_bfloat16* __restrict__ olo) {
    int row = blockIdx.x;
    const float* x = in + (size_t)row * DD;
    float ss = 0.f;
    for (int i = threadIdx.x; i < DD; i += blockDim.x) { float v = x[i]; ss += v * v; }
    float tot = blockReduceSum(ss);
    float inv = rsqrtf(tot / (float)DD + 1e-6f);
    for (int i = threadIdx.x; i < DD; i += blockDim.x) {
        float y = w[i] * x[i] * inv;
        out[(size_t)row * DD + i] = y;
        if (SPLIT) {
            __nv_bfloat16 h = __float2bfloat16(y);
            ohi[(size_t)row * DD + i] = h;
            olo[(size_t)row * DD + i] = __float2bfloat16(y - __bfloat162float(h));
        }
    }
}

// ---------------------------------------------------------------------------
// RoPE + SiLU + bf16 split.  u: silu in-place in uvqk.  q,k: rope then split
// to [b,h,s,d] bf16 hi/lo.  v: split to [b,h,s,d] bf16 hi/lo.
// ---------------------------------------------------------------------------
__global__ void rope_split_k(float* __restrict__ uvqk,
                             const float* __restrict__ td,
                             const int* __restrict__ pos_ids,
                             __nv_bfloat16* __restrict__ qhi, __nv_bfloat16* __restrict__ qlo,
                             __nv_bfloat16* __restrict__ khi, __nv_bfloat16* __restrict__ klo,
                             __nv_bfloat16* __restrict__ vhi, __nv_bfloat16* __restrict__ vlo) {
    int t = blockIdx.x;               // token = b*SS + s
    int b = t / SS, s = t - b * SS;
    __shared__ float cs[32], sn[32];
    if (threadIdx.x < 32) {
        float p = (float)pos_ids[t] + 0.1f * logf(td[t] + 1.0f);
        float invf = expf(-logf(10000.0f) * (float)threadIdx.x / 32.0f);
        float f = p * invf;
        cs[threadIdx.x] = cosf(f);
        sn[threadIdx.x] = sinf(f);
    }
    __syncthreads();
    float* row = uvqk + (size_t)t * FOURD;

    // u = silu(u) in place
    for (int i = threadIdx.x; i < DD; i += blockDim.x) {
        float v = row[i];
        row[i] = v / (1.0f + __expf(-v));
    }
    // v split
    for (int i = threadIdx.x; i < DD; i += blockDim.x) {
        float v = row[DD + i];
        int hh = i >> 6, d = i & 63;
        size_t o = ((size_t)(b * HH + hh) * SS + s) * HD + d;
        __nv_bfloat16 h = __float2bfloat16(v);
        vhi[o] = h;
        vlo[o] = __float2bfloat16(v - __bfloat162float(h));
    }
    // q,k rope + split
    for (int p = threadIdx.x; p < HH * 32; p += blockDim.x) {
        int hh = p >> 5, i = p & 31;
        float c = cs[i], sv = sn[i];
        size_t obase = ((size_t)(b * HH + hh) * SS + s) * HD;
        {
            int base = 2 * DD + hh * HD + i;
            float q1 = row[base], q2 = row[base + 32];
            float r1 = q1 * c - q2 * sv;
            float r2 = q2 * c + q1 * sv;
            __nv_bfloat16 h1 = __float2bfloat16(r1), h2 = __float2bfloat16(r2);
            qhi[obase + i] = h1;      qhi[obase + i + 32] = h2;
            qlo[obase + i] = __float2bfloat16(r1 - __bfloat162float(h1));
            qlo[obase + i + 32] = __float2bfloat16(r2 - __bfloat162float(h2));
        }
        {
            int base = 3 * DD + hh * HD + i;
            float k1 = row[base], k2 = row[base + 32];
            float r1 = k1 * c - k2 * sv;
            float r2 = k2 * c + k1 * sv;
            __nv_bfloat16 h1 = __float2bfloat16(r1), h2 = __float2bfloat16(r2);
            khi[obase + i] = h1;      khi[obase + i + 32] = h2;
            klo[obase + i] = __float2bfloat16(r1 - __bfloat162float(h1));
            klo[obase + i + 32] = __float2bfloat16(r2 - __bfloat162float(h2));
        }
    }
}

// ---------------------------------------------------------------------------
// Tensor-core causal SiLU attention, bf16x3.
// grid=(S/128, B*H), 256 threads (8 warps x 16 q-rows).
// K/V tiles 64 keys, 3-stage cp.async pipeline. W split in registers for PV.
// ---------------------------------------------------------------------------
#define AROWB 144                 // 72 elems * 2B, 16B-aligned, 4-bank offset/row
#define QA (128 * AROWB)          // 18432 B per Q array
#define KVA (64 * AROWB)          // 9216 B per KV array
#define KVSTG (4 * KVA)           // 36864 B per stage (khi,klo,vhi,vlo)
#define ATTN_SMEM (2 * QA + 3 * KVSTG)   // 147456 B

__global__ __launch_bounds__(256, 1)
void attn_mma_k(const __nv_bfloat16* __restrict__ qhi, const __nv_bfloat16* __restrict__ qlo,
                const __nv_bfloat16* __restrict__ khi, const __nv_bfloat16* __restrict__ klo,
                const __nv_bfloat16* __restrict__ vhi, const __nv_bfloat16* __restrict__ vlo,
                float* __restrict__ out) {
    extern __shared__ char dynsm[];
    const uint32_t sb = smem_u32(dynsm);
    const int tid = threadIdx.x;
    const int lane = tid & 31, wid = tid >> 5;
    const int qt = blockIdx.x, bh = blockIdx.y;
    const int b = bh >> 4, h = bh & 15;
    const int q0 = qt * 128;
    const int nkt = 2 * qt + 2;

    const size_t hb = (size_t)bh * SS;   // row base in [b,h,s,d] arrays

    // ---- load Q (hi/lo) ----
    {
        const __nv_bfloat16* qsrc[2] = { qhi + (hb + q0) * HD, qlo + (hb + q0) * HD };
        #pragma unroll
        for (int j = 0; j < 8; j++) {
            int idx = tid + 256 * j;
            int arr = idx >> 10, rem = idx & 1023;
            int row = rem >> 3, seg = rem & 7;
            cp_async16(sb + arr * QA + row * AROWB + seg * 16,
                       qsrc[arr] + (size_t)row * HD + seg * 8);
        }
        CP_COMMIT();
    }

    const __nv_bfloat16* kvsrc[4] = { khi + hb * HD, klo + hb * HD,
                                      vhi + hb * HD, vlo + hb * HD };
    auto load_kv = [&](int stage, int kt) {
        const int k0 = kt * 64;
        const uint32_t dbase = sb + 2 * QA + stage * KVSTG;
        #pragma unroll
        for (int j = 0; j < 8; j++) {
            int idx = tid + 256 * j;
            int arr = idx >> 9, rem = idx & 511;
            int row = rem >> 3, seg = rem & 7;
            cp_async16(dbase + arr * KVA + row * AROWB + seg * 16,
                       kvsrc[arr] + (size_t)(k0 + row) * HD + seg * 8);
        }
        CP_COMMIT();
    };

    load_kv(0, 0);
    load_kv(1, 1);

    // fragment offsets
    const uint32_t aoff = (uint32_t)(wid * 16 + (lane & 15)) * AROWB + (lane >> 4) * 16;
    const uint32_t boff = (uint32_t)((lane >> 4) * 8 + (lane & 7)) * AROWB + ((lane >> 3) & 1) * 16;
    const uint32_t voff = (uint32_t)(((lane >> 3) & 1) * 8 + (lane & 7)) * AROWB + (lane >> 4) * 16;

    const int rbase = q0 + wid * 16 + (lane >> 2);   // row of c0,c1 (c2,c3 at +8)
    float o[8][4] = {};

    for (int kt = 0; kt < nkt; kt++) {
        if (kt + 1 < nkt) { CP_WAIT1(); } else { CP_WAIT0(); }
        __syncthreads();

        const int k0 = kt * 64;
        const uint32_t kb = sb + 2 * QA + (kt % 3) * KVSTG;

        if (k0 <= q0 + wid * 16 + 15) {   // not fully masked for this warp
            // ---- S = Q K^T (bf16x3) ----
            float s[8][4] = {};
            #pragma unroll
            for (int ks = 0; ks < 4; ks++) {
                uint32_t aH[4], aL[4];
                ldsm4(aH, sb + aoff + ks * 32);
                ldsm4(aL, sb + QA + aoff + ks * 32);
                #pragma unroll
                for (int p = 0; p < 4; p++) {
                    uint32_t bH[4], bL[4];
                    uint32_t ba = kb + boff + p * (16 * AROWB) + ks * 32;
                    ldsm4(bH, ba);
                    ldsm4(bL, ba + KVA);
                    #pragma unroll
                    for (int half = 0; half < 2; half++) {
                        float* acc = s[2 * p + half];
                        mma_bf16(acc, aH, &bH[half * 2]);
                        mma_bf16(acc, aH, &bL[half * 2]);
                        mma_bf16(acc, aL, &bH[half * 2]);
                    }
                }
            }
            // ---- silu + causal mask ----
            const bool needmask = (k0 + 63 > q0 + wid * 16);
            #pragma unroll
            for (int n = 0; n < 8; n++) {
                int col0 = k0 + 8 * n + (lane & 3) * 2;
                #pragma unroll
                for (int e = 0; e < 4; e++) {
                    int r = rbase + ((e >> 1) ? 8 : 0);
                    int c = col0 + (e & 1);
                    float v = s[n][e] * 0.125f;
                    v = v / (1.0f + __expf(-v));
                    if (needmask && c > r) v = 0.0f;
                    s[n][e] = v;
                }
            }
            // ---- O += W V (bf16x3, W split in registers) ----
            #pragma unroll
            for (int kk = 0; kk < 4; kk++) {
                const float* t0 = s[2 * kk];
                const float* t1 = s[2 * kk + 1];
                float h00 = __bfloat162float(__float2bfloat16(t0[0]));
                float h01 = __bfloat162float(__float2bfloat16(t0[1]));
                float h02 = __bfloat162float(__float2bfloat16(t0[2]));
                float h03 = __bfloat162float(__float2bfloat16(t0[3]));
                float h10 = __bfloat162float(__float2bfloat16(t1[0]));
                float h11 = __bfloat162float(__float2bfloat16(t1[1]));
                float h12 = __bfloat162float(__float2bfloat16(t1[2]));
                float h13 = __bfloat162float(__float2bfloat16(t1[3]));
                uint32_t wh[4], wl[4];
                wh[0] = packbf(h00, h01); wh[1] = packbf(h02, h03);
                wh[2] = packbf(h10, h11); wh[3] = packbf(h12, h13);
                wl[0] = packbf(t0[0] - h00, t0[1] - h01);
                wl[1] = packbf(t0[2] - h02, t0[3] - h03);
                wl[2] = packbf(t1[0] - h10, t1[1] - h11);
                wl[3] = packbf(t1[2] - h12, t1[3] - h13);
                #pragma unroll
                for (int dg = 0; dg < 4; dg++) {
                    uint32_t va = kb + 2 * KVA + kk * (16 * AROWB) + voff + dg * 32;
                    uint32_t vH[4], vL[4];
                    ldsm4t(vH, va);
                    ldsm4t(vL, va + KVA);
                    #pragma unroll
                    for (int half = 0; half < 2; half++) {
                        float* acc = o[2 * dg + half];
                        mma_bf16(acc, wh, &vH[half * 2]);
                        mma_bf16(acc, wh, &vL[half * 2]);
                        mma_bf16(acc, wl, &vH[half * 2]);
                    }
                }
            }
        }

        if (kt + 2 < nkt) load_kv((kt + 2) % 3, kt + 2);
    }

    // ---- write out [B,S,D] fp32 ----
    const int row0 = q0 + wid * 16 + (lane >> 2);
    #pragma unroll
    for (int dt = 0; dt < 8; dt++) {
        int col = h * HD + dt * 8 + (lane & 3) * 2;
        *reinterpret_cast<float2*>(out + (size_t)(b * SS + row0) * DD + col) =
            make_float2(o[dt][0], o[dt][1]);
        *reinterpret_cast<float2*>(out + (size_t)(b * SS + row0 + 8) * DD + col) =
            make_float2(o[dt][2], o[dt][3]);
    }
}

// ---------------------------------------------------------------------------
// gated = rms_norm(attn, gate_w) * u  -> bf16 hi/lo split only
// ---------------------------------------------------------------------------
__global__ void rmsgate_k(const float* __restrict__ attn, const float* __restrict__ gw,
                          const float* __restrict__ uvqk,
                          __nv_bfloat16* __restrict__ ghi, __nv_bfloat16* __restrict__ glo) {
    int row = blockIdx.x;
    const float* x = attn + (size_t)row * DD;
    const float* u = uvqk + (size_t)row * FOURD;   // silu(u) at offset 0
    float ss = 0.f;
    for (int i = threadIdx.x; i < DD; i += blockDim.x) { float v = x[i]; ss += v * v; }
    float tot = blockReduceSum(ss);
    float inv = rsqrtf(tot / (float)DD + 1e-6f);
    for (int i = threadIdx.x; i < DD; i += blockDim.x) {
        float y = gw[i] * x[i] * inv * u[i];
        __nv_bfloat16 hh = __float2bfloat16(y);
        ghi[(size_t)row * DD + i] = hh;
        glo[(size_t)row * DD + i] = __float2bfloat16(y - __bfloat162float(hh));
    }
}

// ---------------------------------------------------------------------------
// kernel_launch
// ---------------------------------------------------------------------------
extern "C" void kernel_launch(void* const* d_in, const int* in_sizes, int n_in,
                              void* d_out, int out_size) {
    const float* x        = (const float*)d_in[0];
    const float* td       = (const float*)d_in[1];
    // d_in[2] = attn_mask: structurally tril(ones) -> causal mask applied in-kernel
    const float* uvqk_w   = (const float*)d_in[3];
    const float* uvqk_b   = (const float*)d_in[4];
    const float* gate_w   = (const float*)d_in[5];
    const float* out_w    = (const float*)d_in[6];
    const float* out_b    = (const float*)d_in[7];
    const float* in_nw    = (const float*)d_in[8];
    const float* last_nw  = (const float*)d_in[9];
    const int*   pos_ids  = (const int*)d_in[10];
    float* out = (float*)d_out;

    void *ph, *puvqk, *pattn;
    void *pwqh, *pwql, *pwoh, *pwol, *pahi, *palo, *pghi, *pglo;
    void *pqh, *pql, *pkh, *pkl, *pvh, *pvl;
    cudaGetSymbolAddress(&ph, g_h);
    cudaGetSymbolAddress(&puvqk, g_uvqk);
    cudaGetSymbolAddress(&pattn, g_attn);
    cudaGetSymbolAddress(&pwqh, g_wqk_hi);
    cudaGetSymbolAddress(&pwql, g_wqk_lo);
    cudaGetSymbolAddress(&pwoh, g_wo_hi);
    cudaGetSymbolAddress(&pwol, g_wo_lo);
    cudaGetSymbolAddress(&pahi, g_ahi);
    cudaGetSymbolAddress(&palo, g_alo);
    cudaGetSymbolAddress(&pghi, g_ghi);
    cudaGetSymbolAddress(&pglo, g_glo);
    cudaGetSymbolAddress(&pqh, g_qhi);
    cudaGetSymbolAddress(&pql, g_qlo);
    cudaGetSymbolAddress(&pkh, g_khi);
    cudaGetSymbolAddress(&pkl, g_klo);
    cudaGetSymbolAddress(&pvh, g_vhi);
    cudaGetSymbolAddress(&pvl, g_vlo);
    float* h    = (float*)ph;
    float* uvqk = (float*)puvqk;
    float* attn = (float*)pattn;
    __nv_bfloat16* wqh = (__nv_bfloat16*)pwqh;
    __nv_bfloat16* wql = (__nv_bfloat16*)pwql;
    __nv_bfloat16* woh = (__nv_bfloat16*)pwoh;
    __nv_bfloat16* wol = (__nv_bfloat16*)pwol;
    __nv_bfloat16* ahi = (__nv_bfloat16*)pahi;
    __nv_bfloat16* alo = (__nv_bfloat16*)palo;
    __nv_bfloat16* ghi = (__nv_bfloat16*)pghi;
    __nv_bfloat16* glo = (__nv_bfloat16*)pglo;
    __nv_bfloat16* qhi = (__nv_bfloat16*)pqh;
    __nv_bfloat16* qlo = (__nv_bfloat16*)pql;
    __nv_bfloat16* khi = (__nv_bfloat16*)pkh;
    __nv_bfloat16* klo = (__nv_bfloat16*)pkl;
    __nv_bfloat16* vhi = (__nv_bfloat16*)pvh;
    __nv_bfloat16* vlo = (__nv_bfloat16*)pvl;

    cudaFuncSetAttribute(attn_mma_k, cudaFuncAttributeMaxDynamicSharedMemorySize, ATTN_SMEM);
    cudaFuncSetAttribute(mmagemm_k<false, false>, cudaFuncAttributeMaxDynamicSharedMemorySize, GSMEM);
    cudaFuncSetAttribute(mmagemm_k<true, true>,   cudaFuncAttributeMaxDynamicSharedMemorySize, GSMEM);
    cudaFuncSetAttribute(mmagemm_k<true, false>,  cudaFuncAttributeMaxDynamicSharedMemorySize, GSMEM);

    // weight convert (transpose + bf16 split), all layers
    wconv_k<<<dim3(FOURD / 32, DD / 32, LL), dim3(32, 8)>>>(uvqk_w, wqh, wql, DD, FOURD);
    wconv_k<<<dim3(DD / 32, DD / 32, LL), dim3(32, 8)>>>(out_w, woh, wol, DD, DD);

    // h = rms_norm(x, in_norm_w), plus bf16 split into ahi/alo
    rmsnorm_k<true><<<MROWS, 256>>>(x, in_nw, h, ahi, alo);

    for (int l = 0; l < LL; l++) {
        const __nv_bfloat16* wqhl = wqh + (size_t)l * FOURD * DD;
        const __nv_bfloat16* wqll = wql + (size_t)l * FOURD * DD;
        const __nv_bfloat16* wohl = woh + (size_t)l * DD * DD;
        const __nv_bfloat16* woll = wol + (size_t)l * DD * DD;
        const float* bl  = uvqk_b + (size_t)l * FOURD;
        const float* gwl = gate_w + (size_t)l * DD;
        const float* obl = out_b + (size_t)l * DD;

        // uvqk = h @ W + b
        mmagemm_k<false, false><<<dim3(FOURD / 128, MROWS / 128), 256, GSMEM>>>(
            FOURD, DD, ahi, alo, wqhl, wqll, bl, nullptr, uvqk, nullptr, nullptr);
        // silu(u) in-place; rope(q,k) + split q/k/v to bf16 [b,h,s,d]
        rope_split_k<<<MROWS, 128>>>(uvqk, td, pos_ids, qhi, qlo, khi, klo, vhi, vlo);
        // attention (tensor cores)
        attn_mma_k<<<dim3(SS / 128, BB * HH), 256, ATTN_SMEM>>>(
            qhi, qlo, khi, klo, vhi, vlo, attn);
        // gated = rms_norm(attn, gate_w) * u -> split
        rmsgate_k<<<MROWS, 256>>>(attn, gwl, uvqk, ghi, glo);
        // h = h + g @ out_w + out_b; split h for next layer's GEMM
        if (l + 1 < LL) {
            mmagemm_k<true, true><<<dim3(DD / 128, MROWS / 128), 256, GSMEM>>>(
                DD, DD, ghi, glo, wohl, woll, obl, h, h, ahi, alo);
        } else {
            mmagemm_k<true, false><<<dim3(DD / 128, MROWS / 128), 256, GSMEM>>>(
                DD, DD, ghi, glo, wohl, woll, obl, h, h, nullptr, nullptr);
        }
    }

    rmsnorm_k<false><<<MROWS, 256>>>(h, last_nw, out, nullptr, nullptr);
}